// round 6
// baseline (speedup 1.0000x reference)
#include <cuda_runtime.h>
#include <cstdint>
#include <math.h>

#define L_SEQ  2048
#define BATCH  2
#define DM     1024
#define NH     16
#define DK     64
#define E3     3072
#define MROWS  (L_SEQ * BATCH)
#define HB     (NH * BATCH)     // 32

// Scratch (static device allocations — allowed)
__device__ float g_Q[HB * L_SEQ * DK];   // [hb][l][d]
__device__ float g_K[HB * L_SEQ * DK];   // [hb][l][d]
__device__ float g_V[HB * L_SEQ * DK];   // [hb][l][d]

// ---------------------------------------------------------------------------
// helpers
// ---------------------------------------------------------------------------
__device__ __forceinline__ uint32_t cvt_tf32(float x) {
    uint32_t u;
    asm("cvt.rna.tf32.f32 %0, %1;" : "=r"(u) : "f"(x));
    return u;
}

// D += A(16x8) * B(8x8), tf32 inputs, f32 accum
__device__ __forceinline__ void mma_tf32(float* d, const uint32_t* a, const uint32_t* b) {
    asm volatile(
        "mma.sync.aligned.m16n8k8.row.col.f32.tf32.tf32.f32 "
        "{%0,%1,%2,%3}, {%4,%5,%6,%7}, {%8,%9}, {%0,%1,%2,%3};"
        : "+f"(d[0]), "+f"(d[1]), "+f"(d[2]), "+f"(d[3])
        : "r"(a[0]), "r"(a[1]), "r"(a[2]), "r"(a[3]), "r"(b[0]), "r"(b[1]));
}

// fast exp on the FMA pipe; input effectively <= 0
__device__ __forceinline__ float fexp(float x) {
    x = fmaxf(x, -80.0f);
    float t = x * 1.4426950408889634f;
    float n = rintf(t);
    float r = fmaf(n, -0.6931471805599453f, x);
    float p = fmaf(r, 0.00833333333f, 0.04166666667f);
    p = fmaf(p, r, 0.16666666667f);
    p = fmaf(p, r, 0.5f);
    p = fmaf(p, r, 1.0f);
    p = fmaf(p, r, 1.0f);
    return p * __int_as_float(((int)n + 127) << 23);
}

// ---------------------------------------------------------------------------
// Kernel 1: QKV projection (tf32 mma.sync) with FUSED RoPE epilogue.
// CTA tile 128x128, BK=32, double-buffered smem, 8 warps (2x4), warp tile
// 64x32.  Smem stored k-INTERLEAVED: within each 8-col block, column d with
// low3 = j + 4h is stored at position 2j + h, so an mma fragment's two words
// (kk+j, kk+j+4) are adjacent -> single ld.shared.v2.
// ---------------------------------------------------------------------------
#define QKV_SMEM 73728   // 2 arrays * 2 buffers * 128*36 words * 4B
__global__ __launch_bounds__(256, 2) void qkv_mma_kernel(
    const float* __restrict__ X, const float* __restrict__ W)
{
    extern __shared__ uint32_t sm32[];
    uint32_t* SA = sm32;          // [buf][128][36]
    uint32_t* SB = sm32 + 9216;   // [buf][128][36]

    const int tid  = threadIdx.x;
    const int lane = tid & 31;
    const int w    = tid >> 5;
    const int wm   = w >> 2;       // 0..1
    const int wn   = w & 3;        // 0..3
    const int g    = lane >> 2;    // 0..7
    const int j    = lane & 3;     // 0..3

    const int m0 = blockIdx.y * 128;
    const int n0 = blockIdx.x * 128;

    // staging mapping: idx = tid + it*256 (it 0..1), r = idx>>2 (0..127),
    // kk = (idx&3)*8 — each thread covers one full 8-col block (2 float4).
    const int st_r0 = tid >> 2;
    const int st_kk = (tid & 3) * 8;
    const int st_r1 = (tid + 256) >> 2;

    float acc[4][4][4];
#pragma unroll
    for (int mt = 0; mt < 4; mt++)
#pragma unroll
        for (int nt = 0; nt < 4; nt++)
#pragma unroll
            for (int e = 0; e < 4; e++) acc[mt][nt][e] = 0.f;

    float4 a4[2][2], b4[2][2];   // [it][half]

#define QKV_LDG(k0)                                                            \
    {                                                                          \
        a4[0][0] = *(const float4*)(X + (size_t)(m0 + st_r0) * DM + (k0) + st_kk);     \
        a4[0][1] = *(const float4*)(X + (size_t)(m0 + st_r0) * DM + (k0) + st_kk + 4); \
        b4[0][0] = *(const float4*)(W + (size_t)(n0 + st_r0) * DM + (k0) + st_kk);     \
        b4[0][1] = *(const float4*)(W + (size_t)(n0 + st_r0) * DM + (k0) + st_kk + 4); \
        a4[1][0] = *(const float4*)(X + (size_t)(m0 + st_r1) * DM + (k0) + st_kk);     \
        a4[1][1] = *(const float4*)(X + (size_t)(m0 + st_r1) * DM + (k0) + st_kk + 4); \
        b4[1][0] = *(const float4*)(W + (size_t)(n0 + st_r1) * DM + (k0) + st_kk);     \
        b4[1][1] = *(const float4*)(W + (size_t)(n0 + st_r1) * DM + (k0) + st_kk + 4); \
    }

#define QKV_STS(buf)                                                           \
    {                                                                          \
        uint32_t* Ad = SA + (buf) * 4608;                                      \
        uint32_t* Bd = SB + (buf) * 4608;                                      \
        const float* fa0 = (const float*)&a4[0][0];                            \
        const float* fa1 = (const float*)&a4[0][1];                            \
        const float* fb0 = (const float*)&b4[0][0];                            \
        const float* fb1 = (const float*)&b4[0][1];                            \
        _Pragma("unroll")                                                      \
        for (int jj = 0; jj < 4; jj++) {                                       \
            *(uint2*)&Ad[st_r0 * 36 + st_kk + 2 * jj] =                        \
                make_uint2(cvt_tf32(fa0[jj]), cvt_tf32(fa1[jj]));              \
            *(uint2*)&Bd[st_r0 * 36 + st_kk + 2 * jj] =                        \
                make_uint2(cvt_tf32(fb0[jj]), cvt_tf32(fb1[jj]));              \
        }                                                                      \
        fa0 = (const float*)&a4[1][0]; fa1 = (const float*)&a4[1][1];          \
        fb0 = (const float*)&b4[1][0]; fb1 = (const float*)&b4[1][1];          \
        _Pragma("unroll")                                                      \
        for (int jj = 0; jj < 4; jj++) {                                       \
            *(uint2*)&Ad[st_r1 * 36 + st_kk + 2 * jj] =                        \
                make_uint2(cvt_tf32(fa0[jj]), cvt_tf32(fa1[jj]));              \
            *(uint2*)&Bd[st_r1 * 36 + st_kk + 2 * jj] =                        \
                make_uint2(cvt_tf32(fb0[jj]), cvt_tf32(fb1[jj]));              \
        }                                                                      \
    }

    QKV_LDG(0);
    QKV_STS(0);
    __syncthreads();

    for (int s = 0; s < 32; s++) {
        if (s < 31) QKV_LDG((s + 1) * 32);

        const uint32_t* Ab = SA + (s & 1) * 4608;
        const uint32_t* Bb = SB + (s & 1) * 4608;
#pragma unroll
        for (int ks = 0; ks < 4; ks++) {
            const int kk2 = ks * 8 + 2 * j;
            uint32_t af[4][4];
#pragma unroll
            for (int mt = 0; mt < 4; mt++) {
                int row = wm * 64 + mt * 16 + g;
                uint2 l0 = *(const uint2*)&Ab[row * 36 + kk2];        // (a0, a2)
                uint2 l1 = *(const uint2*)&Ab[(row + 8) * 36 + kk2];  // (a1, a3)
                af[mt][0] = l0.x; af[mt][1] = l1.x;
                af[mt][2] = l0.y; af[mt][3] = l1.y;
            }
#pragma unroll
            for (int nt = 0; nt < 4; nt++) {
                int col = wn * 32 + nt * 8 + g;
                uint2 lb = *(const uint2*)&Bb[col * 36 + kk2];
                uint32_t bf[2] = { lb.x, lb.y };
#pragma unroll
                for (int mt = 0; mt < 4; mt++)
                    mma_tf32(acc[mt][nt], af[mt], bf);
            }
        }
        if (s < 31) {
            QKV_STS((s + 1) & 1);
            __syncthreads();
        }
    }

    // ---- fused RoPE on accumulators (q and k columns only) ----
    if ((wn & 1) == 0) {
        float thc[2][2];
#pragma unroll
        for (int nt = 0; nt < 2; nt++)
#pragma unroll
            for (int e = 0; e < 2; e++) {
                int d = nt * 8 + 2 * j + e;
                thc[nt][e] = powf(10000.0f, -(float)d * (1.0f / 16.0f));
            }
#pragma unroll
        for (int nt = 0; nt < 2; nt++) {
            int col = n0 + wn * 32 + nt * 8 + 2 * j;
            int h   = col / 192;
            int jj  = col - h * 192;
            int t   = jj >> 6;
            if (t < 2) {   // q or k column
#pragma unroll
                for (int mt = 0; mt < 4; mt++) {
#pragma unroll
                    for (int rr = 0; rr < 2; rr++) {
                        int row = m0 + wm * 64 + mt * 16 + g + rr * 8;
                        float lf = (float)(row >> 1);
#pragma unroll
                        for (int e = 0; e < 2; e++) {
                            float sn, cs;
                            sincosf(lf * thc[nt][e], &sn, &cs);
                            float x1 = acc[mt][nt][rr * 2 + e];
                            float x2 = acc[mt][nt + 2][rr * 2 + e];
                            acc[mt][nt][rr * 2 + e]     = x1 * cs - x2 * sn;
                            acc[mt][nt + 2][rr * 2 + e] = x2 * cs + x1 * sn;
                        }
                    }
                }
            }
        }
    }

    // ---- epilogue scatter ----
#pragma unroll
    for (int mt = 0; mt < 4; mt++) {
#pragma unroll
        for (int nt = 0; nt < 4; nt++) {
            int col = n0 + wn * 32 + nt * 8 + 2 * j;
            int h   = col / 192;
            int jj  = col - h * 192;
            int t   = jj >> 6;
            int d   = jj & 63;
#pragma unroll
            for (int rr = 0; rr < 2; rr++) {
                int row = m0 + wm * 64 + mt * 16 + g + rr * 8;
                int l = row >> 1, b = row & 1;
                int hb = h * 2 + b;
                float2 v = make_float2(acc[mt][nt][rr * 2], acc[mt][nt][rr * 2 + 1]);
                float* dst = (t == 0) ? g_Q : (t == 1) ? g_K : g_V;
                *(float2*)&dst[(((size_t)hb * L_SEQ) + l) * DK + d] = v;
            }
        }
    }
}

// ---------------------------------------------------------------------------
// Kernel 2: fused flash attention, tf32 mma.sync.
// CTA: 128 q rows x one (h,b). 8 warps x 16 q-rows, 2 CTAs/SM.
// K smem is k-interleaved (v2 fragment loads); V smem is [key][d]
// (conflict-free scalar loads); P is warp-private.
// Double-buffered K/V -> ONE syncthreads per 64-key chunk.
// LDG for chunk kc+1 issued after P-store (s[] dead), STS after PV mma.
// ---------------------------------------------------------------------------
#define KST 68
#define VST 72
#define KBUF (64 * KST)
#define VBUF (64 * VST)
#define FLASH_SMEM ((2 * KBUF + 2 * VBUF + 128 * KST) * 4)   // 106496 B

__global__ __launch_bounds__(256, 2) void flash_kernel(float* __restrict__ out)
{
    extern __shared__ uint32_t fsm[];
    uint32_t* Kb0 = fsm;                       // [2][64][KST]
    uint32_t* Vb0 = fsm + 2 * KBUF;            // [2][64][VST]
    uint32_t* Ps  = fsm + 2 * KBUF + 2 * VBUF; // [128][KST]

    const int tid  = threadIdx.x;
    const int lane = tid & 31;
    const int w    = tid >> 5;     // 0..7
    const int g    = lane >> 2;
    const int j    = lane & 3;

    const int q0 = blockIdx.x * 128;
    const int hb = blockIdx.y;
    const int h  = hb >> 1, b = hb & 1;

    const float* Qg = g_Q + (size_t)hb * L_SEQ * DK;
    const float* Kg = g_K + (size_t)hb * L_SEQ * DK;
    const float* Vg = g_V + (size_t)hb * L_SEQ * DK;

    // K staging mapping: idx = tid + it*256 (it 0..1): r = idx>>3, kk = (idx&7)*8
    const int kst_r0 = tid >> 3;
    const int kst_kk = (tid & 7) * 8;
    const int kst_r1 = (tid + 256) >> 3;

    // Q fragments (x 1/8 scale), registers for all chunks
    uint32_t qa[8][4];
    {
        int r0 = q0 + w * 16 + g;
#pragma unroll
        for (int ks = 0; ks < 8; ks++) {
            int c = ks * 8 + j;
            qa[ks][0] = cvt_tf32(Qg[(size_t)r0 * DK + c] * 0.125f);
            qa[ks][1] = cvt_tf32(Qg[(size_t)(r0 + 8) * DK + c] * 0.125f);
            qa[ks][2] = cvt_tf32(Qg[(size_t)r0 * DK + c + 4] * 0.125f);
            qa[ks][3] = cvt_tf32(Qg[(size_t)(r0 + 8) * DK + c + 4] * 0.125f);
        }
    }

    float o[8][4];
#pragma unroll
    for (int nt = 0; nt < 8; nt++)
#pragma unroll
        for (int e = 0; e < 4; e++) o[nt][e] = 0.f;
    float mrow0 = -1e30f, mrow1 = -1e30f;
    float lrow0 = 0.f, lrow1 = 0.f;

    float4 ka[2][2];   // K: [it][half-of-8-block]
    float4 vv[4];      // V: old mapping

#define FL_LDG(roff)                                                            \
    {                                                                           \
        ka[0][0] = *(const float4*)(Kg + ((roff) + kst_r0) * DK + kst_kk);      \
        ka[0][1] = *(const float4*)(Kg + ((roff) + kst_r0) * DK + kst_kk + 4);  \
        ka[1][0] = *(const float4*)(Kg + ((roff) + kst_r1) * DK + kst_kk);      \
        ka[1][1] = *(const float4*)(Kg + ((roff) + kst_r1) * DK + kst_kk + 4);  \
        _Pragma("unroll")                                                       \
        for (int it = 0; it < 4; it++) {                                        \
            int idx = tid + it * 256;                                           \
            int r = idx >> 4, c4 = (idx & 15) * 4;                              \
            vv[it] = *(const float4*)(Vg + ((roff) + r) * DK + c4);             \
        }                                                                       \
    }

#define FL_STS(buf)                                                             \
    {                                                                           \
        uint32_t* Kd = Kb0 + (buf) * KBUF;                                      \
        uint32_t* Vd = Vb0 + (buf) * VBUF;                                      \
        const float* f0 = (const float*)&ka[0][0];                              \
        const float* f1 = (const float*)&ka[0][1];                              \
        _Pragma("unroll")                                                       \
        for (int jj = 0; jj < 4; jj++)                                          \
            *(uint2*)&Kd[kst_r0 * KST + kst_kk + 2 * jj] =                      \
                make_uint2(cvt_tf32(f0[jj]), cvt_tf32(f1[jj]));                 \
        f0 = (const float*)&ka[1][0]; f1 = (const float*)&ka[1][1];             \
        _Pragma("unroll")                                                       \
        for (int jj = 0; jj < 4; jj++)                                          \
            *(uint2*)&Kd[kst_r1 * KST + kst_kk + 2 * jj] =                      \
                make_uint2(cvt_tf32(f0[jj]), cvt_tf32(f1[jj]));                 \
        _Pragma("unroll")                                                       \
        for (int it = 0; it < 4; it++) {                                        \
            int idx = tid + it * 256;                                           \
            int r = idx >> 4, c4 = (idx & 15) * 4;                              \
            *(uint4*)&Vd[r * VST + c4] =                                        \
                make_uint4(cvt_tf32(vv[it].x), cvt_tf32(vv[it].y),              \
                           cvt_tf32(vv[it].z), cvt_tf32(vv[it].w));             \
        }                                                                       \
    }

    // prologue: stage chunk 0 into buffer 0
    FL_LDG((size_t)0);
    FL_STS(0);
    __syncthreads();

    for (int kc = 0; kc < L_SEQ / 64; kc++) {
        const uint32_t* Ks = Kb0 + (kc & 1) * KBUF;
        const uint32_t* Vs = Vb0 + (kc & 1) * VBUF;

        // S = Q K^T  (per warp: 16 x 64), v2 fragment loads
        float s[8][4];
#pragma unroll
        for (int nt = 0; nt < 8; nt++)
#pragma unroll
            for (int e = 0; e < 4; e++) s[nt][e] = 0.f;
#pragma unroll
        for (int ks = 0; ks < 8; ks++) {
            const int kk2 = ks * 8 + 2 * j;
#pragma unroll
            for (int nt = 0; nt < 8; nt++) {
                uint2 lb = *(const uint2*)&Ks[(nt * 8 + g) * KST + kk2];
                uint32_t bf[2] = { lb.x, lb.y };
                mma_tf32(s[nt], qa[ks], bf);
            }
        }

        // online softmax
        float mx0 = -1e30f, mx1 = -1e30f;
#pragma unroll
        for (int nt = 0; nt < 8; nt++) {
            mx0 = fmaxf(mx0, fmaxf(s[nt][0], s[nt][1]));
            mx1 = fmaxf(mx1, fmaxf(s[nt][2], s[nt][3]));
        }
        mx0 = fmaxf(mx0, __shfl_xor_sync(0xffffffffu, mx0, 1));
        mx0 = fmaxf(mx0, __shfl_xor_sync(0xffffffffu, mx0, 2));
        mx1 = fmaxf(mx1, __shfl_xor_sync(0xffffffffu, mx1, 1));
        mx1 = fmaxf(mx1, __shfl_xor_sync(0xffffffffu, mx1, 2));

        float mn0 = fmaxf(mrow0, mx0), mn1 = fmaxf(mrow1, mx1);
        float al0 = fexp(mrow0 - mn0), al1 = fexp(mrow1 - mn1);
        mrow0 = mn0; mrow1 = mn1;

        float rs0 = 0.f, rs1 = 0.f;
#pragma unroll
        for (int nt = 0; nt < 8; nt++) {
            s[nt][0] = fexp(s[nt][0] - mn0);
            s[nt][1] = fexp(s[nt][1] - mn0);
            s[nt][2] = fexp(s[nt][2] - mn1);
            s[nt][3] = fexp(s[nt][3] - mn1);
            rs0 += s[nt][0] + s[nt][1];
            rs1 += s[nt][2] + s[nt][3];
        }
        rs0 += __shfl_xor_sync(0xffffffffu, rs0, 1);
        rs0 += __shfl_xor_sync(0xffffffffu, rs0, 2);
        rs1 += __shfl_xor_sync(0xffffffffu, rs1, 1);
        rs1 += __shfl_xor_sync(0xffffffffu, rs1, 2);
        lrow0 = lrow0 * al0 + rs0;
        lrow1 = lrow1 * al1 + rs1;

#pragma unroll
        for (int nt = 0; nt < 8; nt++) {
            o[nt][0] *= al0; o[nt][1] *= al0;
            o[nt][2] *= al1; o[nt][3] *= al1;
        }

        // write P (warp-private rows, no sync)
        {
            int pr0 = (w * 16 + g) * KST;
            int pr1 = (w * 16 + g + 8) * KST;
#pragma unroll
            for (int nt = 0; nt < 8; nt++) {
                int c = nt * 8 + 2 * j;
                *(uint2*)&Ps[pr0 + c] = make_uint2(cvt_tf32(s[nt][0]), cvt_tf32(s[nt][1]));
                *(uint2*)&Ps[pr1 + c] = make_uint2(cvt_tf32(s[nt][2]), cvt_tf32(s[nt][3]));
            }
        }

        // prefetch next chunk (s[] dead now — low reg pressure window)
        if (kc + 1 < L_SEQ / 64) FL_LDG((size_t)(kc + 1) * 64);

        // O += P V
#pragma unroll
        for (int ks = 0; ks < 8; ks++) {
            const int kk = ks * 8;
            uint32_t pa[4];
            pa[0] = Ps[(w * 16 + g) * KST + kk + j];
            pa[1] = Ps[(w * 16 + g + 8) * KST + kk + j];
            pa[2] = Ps[(w * 16 + g) * KST + kk + j + 4];
            pa[3] = Ps[(w * 16 + g + 8) * KST + kk + j + 4];
#pragma unroll
            for (int nt = 0; nt < 8; nt++) {
                uint32_t bf[2] = { Vs[(kk + j) * VST + nt * 8 + g],
                                   Vs[(kk + j + 4) * VST + nt * 8 + g] };
                mma_tf32(o[nt], pa, bf);
            }
        }

        // stage next chunk into the idle buffer, then single barrier
        if (kc + 1 < L_SEQ / 64) FL_STS((kc + 1) & 1);
        __syncthreads();
    }

    // normalize and write out: out[l][b][h*64 + d]
    float inv0 = 1.0f / lrow0, inv1 = 1.0f / lrow1;
    int r0 = q0 + w * 16 + g;
#pragma unroll
    for (int nt = 0; nt < 8; nt++) {
        int c = nt * 8 + 2 * j;
        float2 v0 = make_float2(o[nt][0] * inv0, o[nt][1] * inv0);
        *(float2*)(out + ((size_t)r0 * BATCH + b) * DM + h * DK + c) = v0;
        float2 v1 = make_float2(o[nt][2] * inv1, o[nt][3] * inv1);
        *(float2*)(out + ((size_t)(r0 + 8) * BATCH + b) * DM + h * DK + c) = v1;
    }
}

// ---------------------------------------------------------------------------
extern "C" void kernel_launch(void* const* d_in, const int* in_sizes, int n_in,
                              void* d_out, int out_size)
{
    const float* X = (const float*)d_in[0];
    const float* W = (const float*)d_in[1];
    float* out = (float*)d_out;

    cudaFuncSetAttribute(qkv_mma_kernel,
                         cudaFuncAttributeMaxDynamicSharedMemorySize, QKV_SMEM);
    cudaFuncSetAttribute(flash_kernel,
                         cudaFuncAttributeMaxDynamicSharedMemorySize, FLASH_SMEM);

    qkv_mma_kernel<<<dim3(E3 / 128, MROWS / 128), 256, QKV_SMEM>>>(X, W);
    flash_kernel<<<dim3(L_SEQ / 128, HB), 256, FLASH_SMEM>>>(out);
}

// round 7
// speedup vs baseline: 1.3910x; 1.3910x over previous
#include <cuda_runtime.h>
#include <cstdint>
#include <math.h>

#define L_SEQ  2048
#define BATCH  2
#define DM     1024
#define NH     16
#define DK     64
#define E3     3072
#define MROWS  (L_SEQ * BATCH)
#define HB     (NH * BATCH)     // 32

// Scratch (static device allocations — allowed)
__device__ float g_Q[HB * L_SEQ * DK];   // [hb][l][d]
__device__ float g_K[HB * L_SEQ * DK];   // [hb][l][d]
__device__ float g_V[HB * L_SEQ * DK];   // [hb][l][d]

// ---------------------------------------------------------------------------
// helpers
// ---------------------------------------------------------------------------
__device__ __forceinline__ uint32_t cvt_tf32(float x) {
    uint32_t u;
    asm("cvt.rna.tf32.f32 %0, %1;" : "=r"(u) : "f"(x));
    return u;
}

// D += A(16x8) * B(8x8), tf32 inputs, f32 accum
__device__ __forceinline__ void mma_tf32(float* d, const uint32_t* a, const uint32_t* b) {
    asm volatile(
        "mma.sync.aligned.m16n8k8.row.col.f32.tf32.tf32.f32 "
        "{%0,%1,%2,%3}, {%4,%5,%6,%7}, {%8,%9}, {%0,%1,%2,%3};"
        : "+f"(d[0]), "+f"(d[1]), "+f"(d[2]), "+f"(d[3])
        : "r"(a[0]), "r"(a[1]), "r"(a[2]), "r"(a[3]), "r"(b[0]), "r"(b[1]));
}

// ---------------------------------------------------------------------------
// Kernel 1: QKV projection (tf32 mma.sync) with FUSED RoPE epilogue.
// C[m,n] = sum_k X[m,k] * W[n,k].  CTA tile 128x128, BK=32, double-buffered
// smem (1 sync per k-step), 8 warps (2x4), warp tile 64x32.
// Scalar smem fragment loads (conflict-free, stride 36).
// ---------------------------------------------------------------------------
#define QKV_SMEM 73728   // 2 arrays * 2 buffers * 128*36 words * 4B
__global__ __launch_bounds__(256, 2) void qkv_mma_kernel(
    const float* __restrict__ X, const float* __restrict__ W)
{
    extern __shared__ uint32_t sm32[];
    uint32_t* SA = sm32;          // [buf][128][36]
    uint32_t* SB = sm32 + 9216;   // [buf][128][36]

    const int tid  = threadIdx.x;
    const int lane = tid & 31;
    const int w    = tid >> 5;
    const int wm   = w >> 2;       // 0..1
    const int wn   = w & 3;        // 0..3
    const int g    = lane >> 2;    // 0..7
    const int j    = lane & 3;     // 0..3

    const int m0 = blockIdx.y * 128;
    const int n0 = blockIdx.x * 128;

    float acc[4][4][4];
#pragma unroll
    for (int mt = 0; mt < 4; mt++)
#pragma unroll
        for (int nt = 0; nt < 4; nt++)
#pragma unroll
            for (int e = 0; e < 4; e++) acc[mt][nt][e] = 0.f;

    float4 va[4], vb[4];
    // prologue: load + stage k-step 0 into buffer 0
#pragma unroll
    for (int it = 0; it < 4; it++) {
        int idx = tid + it * 256;
        int r   = idx >> 3;
        int c4  = (idx & 7) * 4;
        va[it] = *(const float4*)(X + (size_t)(m0 + r) * DM + c4);
        vb[it] = *(const float4*)(W + (size_t)(n0 + r) * DM + c4);
    }
#pragma unroll
    for (int it = 0; it < 4; it++) {
        int idx = tid + it * 256;
        int r   = idx >> 3;
        int c4  = (idx & 7) * 4;
        uint32_t* pa = SA + r * 36 + c4;
        pa[0] = cvt_tf32(va[it].x); pa[1] = cvt_tf32(va[it].y);
        pa[2] = cvt_tf32(va[it].z); pa[3] = cvt_tf32(va[it].w);
        uint32_t* pb = SB + r * 36 + c4;
        pb[0] = cvt_tf32(vb[it].x); pb[1] = cvt_tf32(vb[it].y);
        pb[2] = cvt_tf32(vb[it].z); pb[3] = cvt_tf32(vb[it].w);
    }
    __syncthreads();

    for (int s = 0; s < 32; s++) {
        if (s < 31) {
            const int k0 = (s + 1) * 32;
#pragma unroll
            for (int it = 0; it < 4; it++) {
                int idx = tid + it * 256;
                int r   = idx >> 3;
                int c4  = (idx & 7) * 4;
                va[it] = *(const float4*)(X + (size_t)(m0 + r) * DM + k0 + c4);
                vb[it] = *(const float4*)(W + (size_t)(n0 + r) * DM + k0 + c4);
            }
        }
        const uint32_t* Ab = SA + (s & 1) * 4608;
        const uint32_t* Bb = SB + (s & 1) * 4608;
#pragma unroll
        for (int ks = 0; ks < 4; ks++) {
            const int kk = ks * 8;
            uint32_t af[4][4];
#pragma unroll
            for (int mt = 0; mt < 4; mt++) {
                int row = wm * 64 + mt * 16 + g;
                af[mt][0] = Ab[row * 36 + kk + j];
                af[mt][1] = Ab[(row + 8) * 36 + kk + j];
                af[mt][2] = Ab[row * 36 + kk + j + 4];
                af[mt][3] = Ab[(row + 8) * 36 + kk + j + 4];
            }
#pragma unroll
            for (int nt = 0; nt < 4; nt++) {
                int col = wn * 32 + nt * 8 + g;
                uint32_t bf[2] = { Bb[col * 36 + kk + j], Bb[col * 36 + kk + j + 4] };
#pragma unroll
                for (int mt = 0; mt < 4; mt++)
                    mma_tf32(acc[mt][nt], af[mt], bf);
            }
        }
        if (s < 31) {
            uint32_t* An = SA + ((s + 1) & 1) * 4608;
            uint32_t* Bn = SB + ((s + 1) & 1) * 4608;
#pragma unroll
            for (int it = 0; it < 4; it++) {
                int idx = tid + it * 256;
                int r   = idx >> 3;
                int c4  = (idx & 7) * 4;
                uint32_t* pa = An + r * 36 + c4;
                pa[0] = cvt_tf32(va[it].x); pa[1] = cvt_tf32(va[it].y);
                pa[2] = cvt_tf32(va[it].z); pa[3] = cvt_tf32(va[it].w);
                uint32_t* pb = Bn + r * 36 + c4;
                pb[0] = cvt_tf32(vb[it].x); pb[1] = cvt_tf32(vb[it].y);
                pb[2] = cvt_tf32(vb[it].z); pb[3] = cvt_tf32(vb[it].w);
            }
            __syncthreads();
        }
    }

    // ---- fused RoPE on accumulators (q and k columns only) ----
    if ((wn & 1) == 0) {
        float thc[2][2];
#pragma unroll
        for (int nt = 0; nt < 2; nt++)
#pragma unroll
            for (int e = 0; e < 2; e++) {
                int d = nt * 8 + 2 * j + e;
                thc[nt][e] = powf(10000.0f, -(float)d * (1.0f / 16.0f));
            }
#pragma unroll
        for (int nt = 0; nt < 2; nt++) {
            int col = n0 + wn * 32 + nt * 8 + 2 * j;
            int h   = col / 192;
            int jj  = col - h * 192;
            int t   = jj >> 6;
            if (t < 2) {   // q or k column
#pragma unroll
                for (int mt = 0; mt < 4; mt++) {
#pragma unroll
                    for (int rr = 0; rr < 2; rr++) {
                        int row = m0 + wm * 64 + mt * 16 + g + rr * 8;
                        float lf = (float)(row >> 1);
#pragma unroll
                        for (int e = 0; e < 2; e++) {
                            float sn, cs;
                            sincosf(lf * thc[nt][e], &sn, &cs);
                            float x1 = acc[mt][nt][rr * 2 + e];
                            float x2 = acc[mt][nt + 2][rr * 2 + e];
                            acc[mt][nt][rr * 2 + e]     = x1 * cs - x2 * sn;
                            acc[mt][nt + 2][rr * 2 + e] = x2 * cs + x1 * sn;
                        }
                    }
                }
            }
        }
    }

    // ---- epilogue scatter ----
#pragma unroll
    for (int mt = 0; mt < 4; mt++) {
#pragma unroll
        for (int nt = 0; nt < 4; nt++) {
            int col = n0 + wn * 32 + nt * 8 + 2 * j;
            int h   = col / 192;
            int jj  = col - h * 192;
            int t   = jj >> 6;
            int d   = jj & 63;
#pragma unroll
            for (int rr = 0; rr < 2; rr++) {
                int row = m0 + wm * 64 + mt * 16 + g + rr * 8;
                int l = row >> 1, b = row & 1;
                int hb = h * 2 + b;
                float2 v = make_float2(acc[mt][nt][rr * 2], acc[mt][nt][rr * 2 + 1]);
                float* dst = (t == 0) ? g_Q : (t == 1) ? g_K : g_V;
                *(float2*)&dst[(((size_t)hb * L_SEQ) + l) * DK + d] = v;
            }
        }
    }
}

// ---------------------------------------------------------------------------
// Kernel 2: fused flash attention, tf32 mma.sync.
// CTA: 128 q rows x one (h,b). 8 warps x 16 q-rows each, 2 CTAs/SM.
// Separate smem regions for K, V, P (P rows warp-private). 2 syncthreads
// per chunk; K/V for chunk kc+1 prefetched into regs before the PV mma.
// exp via __expf (MUFU pipe) — softmax issue cost ~1/4 of polynomial exp.
// ---------------------------------------------------------------------------
#define KS_STRIDE 68
#define VS_STRIDE 72
#define FLASH_SMEM ((64 * KS_STRIDE + 64 * VS_STRIDE + 128 * KS_STRIDE) * 4) // 70656

__global__ __launch_bounds__(256, 2) void flash_kernel(float* __restrict__ out)
{
    extern __shared__ uint32_t fsm[];
    uint32_t* Ks = fsm;                              // [64][68]
    uint32_t* Vs = fsm + 64 * KS_STRIDE;             // [64][72]
    uint32_t* Ps = fsm + 64 * KS_STRIDE + 64 * VS_STRIDE; // [128][68]

    const int tid  = threadIdx.x;
    const int lane = tid & 31;
    const int w    = tid >> 5;     // 0..7
    const int g    = lane >> 2;
    const int j    = lane & 3;

    const int q0 = blockIdx.x * 128;
    const int hb = blockIdx.y;
    const int h  = hb >> 1, b = hb & 1;

    const float* Qg = g_Q + (size_t)hb * L_SEQ * DK;
    const float* Kg = g_K + (size_t)hb * L_SEQ * DK;
    const float* Vg = g_V + (size_t)hb * L_SEQ * DK;

    // Q fragments (x 1/8 scale), kept in registers for all chunks
    uint32_t qa[8][4];
    {
        int r0 = q0 + w * 16 + g;
#pragma unroll
        for (int ks = 0; ks < 8; ks++) {
            int c = ks * 8 + j;
            qa[ks][0] = cvt_tf32(Qg[(size_t)r0 * DK + c] * 0.125f);
            qa[ks][1] = cvt_tf32(Qg[(size_t)(r0 + 8) * DK + c] * 0.125f);
            qa[ks][2] = cvt_tf32(Qg[(size_t)r0 * DK + c + 4] * 0.125f);
            qa[ks][3] = cvt_tf32(Qg[(size_t)(r0 + 8) * DK + c + 4] * 0.125f);
        }
    }

    float o[8][4];
#pragma unroll
    for (int nt = 0; nt < 8; nt++)
#pragma unroll
        for (int e = 0; e < 4; e++) o[nt][e] = 0.f;
    float mrow0 = -1e30f, mrow1 = -1e30f;
    float lrow0 = 0.f, lrow1 = 0.f;

    float4 pk[4], pv[4];
    // prologue: prefetch chunk 0
#pragma unroll
    for (int it = 0; it < 4; it++) {
        int idx = tid + it * 256;
        int r   = idx >> 4;
        int c4  = (idx & 15) * 4;
        pk[it] = *(const float4*)(Kg + (size_t)r * DK + c4);
        pv[it] = *(const float4*)(Vg + (size_t)r * DK + c4);
    }

    for (int kc = 0; kc < L_SEQ / 64; kc++) {
        __syncthreads();   // all warps done with Ks/Vs of previous chunk
#pragma unroll
        for (int it = 0; it < 4; it++) {
            int idx = tid + it * 256;
            int r   = idx >> 4;
            int c4  = (idx & 15) * 4;
            uint32_t* kp = Ks + r * KS_STRIDE + c4;
            kp[0] = cvt_tf32(pk[it].x); kp[1] = cvt_tf32(pk[it].y);
            kp[2] = cvt_tf32(pk[it].z); kp[3] = cvt_tf32(pk[it].w);
            uint32_t* vp = Vs + r * VS_STRIDE + c4;
            vp[0] = cvt_tf32(pv[it].x); vp[1] = cvt_tf32(pv[it].y);
            vp[2] = cvt_tf32(pv[it].z); vp[3] = cvt_tf32(pv[it].w);
        }
        __syncthreads();

        // S = Q K^T  (per warp: 16 x 64)
        float s[8][4];
#pragma unroll
        for (int nt = 0; nt < 8; nt++)
#pragma unroll
            for (int e = 0; e < 4; e++) s[nt][e] = 0.f;
#pragma unroll
        for (int ks = 0; ks < 8; ks++) {
            const int kk = ks * 8;
#pragma unroll
            for (int nt = 0; nt < 8; nt++) {
                uint32_t bf[2] = { Ks[(nt * 8 + g) * KS_STRIDE + kk + j],
                                   Ks[(nt * 8 + g) * KS_STRIDE + kk + j + 4] };
                mma_tf32(s[nt], qa[ks], bf);
            }
        }

        // online softmax (rows g and g+8 of this warp's 16); exp on MUFU
        float mx0 = -1e30f, mx1 = -1e30f;
#pragma unroll
        for (int nt = 0; nt < 8; nt++) {
            mx0 = fmaxf(mx0, fmaxf(s[nt][0], s[nt][1]));
            mx1 = fmaxf(mx1, fmaxf(s[nt][2], s[nt][3]));
        }
        mx0 = fmaxf(mx0, __shfl_xor_sync(0xffffffffu, mx0, 1));
        mx0 = fmaxf(mx0, __shfl_xor_sync(0xffffffffu, mx0, 2));
        mx1 = fmaxf(mx1, __shfl_xor_sync(0xffffffffu, mx1, 1));
        mx1 = fmaxf(mx1, __shfl_xor_sync(0xffffffffu, mx1, 2));

        float mn0 = fmaxf(mrow0, mx0), mn1 = fmaxf(mrow1, mx1);
        float al0 = __expf(mrow0 - mn0), al1 = __expf(mrow1 - mn1);
        mrow0 = mn0; mrow1 = mn1;

        float rs0 = 0.f, rs1 = 0.f;
#pragma unroll
        for (int nt = 0; nt < 8; nt++) {
            s[nt][0] = __expf(s[nt][0] - mn0);
            s[nt][1] = __expf(s[nt][1] - mn0);
            s[nt][2] = __expf(s[nt][2] - mn1);
            s[nt][3] = __expf(s[nt][3] - mn1);
            rs0 += s[nt][0] + s[nt][1];
            rs1 += s[nt][2] + s[nt][3];
        }
        rs0 += __shfl_xor_sync(0xffffffffu, rs0, 1);
        rs0 += __shfl_xor_sync(0xffffffffu, rs0, 2);
        rs1 += __shfl_xor_sync(0xffffffffu, rs1, 1);
        rs1 += __shfl_xor_sync(0xffffffffu, rs1, 2);
        lrow0 = lrow0 * al0 + rs0;
        lrow1 = lrow1 * al1 + rs1;

#pragma unroll
        for (int nt = 0; nt < 8; nt++) {
            o[nt][0] *= al0; o[nt][1] *= al0;
            o[nt][2] *= al1; o[nt][3] *= al1;
        }

        // write P (tf32) into this warp's private rows — no sync needed
        {
            int pr0 = (w * 16 + g) * KS_STRIDE;
            int pr1 = (w * 16 + g + 8) * KS_STRIDE;
#pragma unroll
            for (int nt = 0; nt < 8; nt++) {
                int c = nt * 8 + 2 * j;
                uint2 p01 = make_uint2(cvt_tf32(s[nt][0]), cvt_tf32(s[nt][1]));
                *(uint2*)&Ps[pr0 + c] = p01;
                uint2 p23 = make_uint2(cvt_tf32(s[nt][2]), cvt_tf32(s[nt][3]));
                *(uint2*)&Ps[pr1 + c] = p23;
            }
        }

        // prefetch next chunk while PV mma runs (s[] dead)
        if (kc + 1 < L_SEQ / 64) {
            const size_t roff = (size_t)(kc + 1) * 64;
#pragma unroll
            for (int it = 0; it < 4; it++) {
                int idx = tid + it * 256;
                int r   = idx >> 4;
                int c4  = (idx & 15) * 4;
                pk[it] = *(const float4*)(Kg + (roff + r) * DK + c4);
                pv[it] = *(const float4*)(Vg + (roff + r) * DK + c4);
            }
        }

        // O += P V
#pragma unroll
        for (int ks = 0; ks < 8; ks++) {
            const int kk = ks * 8;
            uint32_t pa[4];
            pa[0] = Ps[(w * 16 + g) * KS_STRIDE + kk + j];
            pa[1] = Ps[(w * 16 + g + 8) * KS_STRIDE + kk + j];
            pa[2] = Ps[(w * 16 + g) * KS_STRIDE + kk + j + 4];
            pa[3] = Ps[(w * 16 + g + 8) * KS_STRIDE + kk + j + 4];
#pragma unroll
            for (int nt = 0; nt < 8; nt++) {
                uint32_t bf[2] = { Vs[(kk + j) * VS_STRIDE + nt * 8 + g],
                                   Vs[(kk + j + 4) * VS_STRIDE + nt * 8 + g] };
                mma_tf32(o[nt], pa, bf);
            }
        }
    }

    // normalize and write out: out[l][b][h*64 + d]
    float inv0 = 1.0f / lrow0, inv1 = 1.0f / lrow1;
    int r0 = q0 + w * 16 + g;
#pragma unroll
    for (int nt = 0; nt < 8; nt++) {
        int c = nt * 8 + 2 * j;
        float2 v0 = make_float2(o[nt][0] * inv0, o[nt][1] * inv0);
        *(float2*)(out + ((size_t)r0 * BATCH + b) * DM + h * DK + c) = v0;
        float2 v1 = make_float2(o[nt][2] * inv1, o[nt][3] * inv1);
        *(float2*)(out + ((size_t)(r0 + 8) * BATCH + b) * DM + h * DK + c) = v1;
    }
}

// ---------------------------------------------------------------------------
extern "C" void kernel_launch(void* const* d_in, const int* in_sizes, int n_in,
                              void* d_out, int out_size)
{
    const float* X = (const float*)d_in[0];
    const float* W = (const float*)d_in[1];
    float* out = (float*)d_out;

    cudaFuncSetAttribute(qkv_mma_kernel,
                         cudaFuncAttributeMaxDynamicSharedMemorySize, QKV_SMEM);
    cudaFuncSetAttribute(flash_kernel,
                         cudaFuncAttributeMaxDynamicSharedMemorySize, FLASH_SMEM);

    qkv_mma_kernel<<<dim3(E3 / 128, MROWS / 128), 256, QKV_SMEM>>>(X, W);
    flash_kernel<<<dim3(L_SEQ / 128, HB), 256, FLASH_SMEM>>>(out);
}

// round 11
// speedup vs baseline: 1.5493x; 1.1138x over previous
#include <cuda_runtime.h>
#include <cstdint>
#include <math.h>

#define L_SEQ  2048
#define BATCH  2
#define DM     1024
#define NH     16
#define DK     64
#define E3     3072
#define MROWS  (L_SEQ * BATCH)
#define HB     (NH * BATCH)     // 32

// Scratch: Q/K/V stored as TF32 BIT PATTERNS (uint32), scale folded into Q.
__device__ uint32_t g_Q[HB * L_SEQ * DK];   // [hb][l][d]  tf32(q * 0.125)
__device__ uint32_t g_K[HB * L_SEQ * DK];   // [hb][l][d]  tf32(k)
__device__ uint32_t g_V[HB * L_SEQ * DK];   // [hb][l][d]  tf32(v)

// ---------------------------------------------------------------------------
// helpers
// ---------------------------------------------------------------------------
__device__ __forceinline__ uint32_t cvt_tf32(float x) {
    uint32_t u;
    asm("cvt.rna.tf32.f32 %0, %1;" : "=r"(u) : "f"(x));
    return u;
}

// D += A(16x8) * B(8x8), tf32 inputs, f32 accum
__device__ __forceinline__ void mma_tf32(float* d, const uint32_t* a, const uint32_t* b) {
    asm volatile(
        "mma.sync.aligned.m16n8k8.row.col.f32.tf32.tf32.f32 "
        "{%0,%1,%2,%3}, {%4,%5,%6,%7}, {%8,%9}, {%0,%1,%2,%3};"
        : "+f"(d[0]), "+f"(d[1]), "+f"(d[2]), "+f"(d[3])
        : "r"(a[0]), "r"(a[1]), "r"(a[2]), "r"(a[3]), "r"(b[0]), "r"(b[1]));
}

__device__ __forceinline__ uint32_t smem_u32(const void* p) {
    uint32_t a;
    asm("{ .reg .u64 t; cvta.to.shared.u64 t, %1; cvt.u32.u64 %0, t; }"
        : "=r"(a) : "l"(p));
    return a;
}

#define CP_ASYNC16(dst, src) \
    asm volatile("cp.async.ca.shared.global [%0], [%1], 16;" :: "r"(dst), "l"(src))
#define CP_COMMIT() asm volatile("cp.async.commit_group;" ::: "memory")
#define CP_WAIT0()  asm volatile("cp.async.wait_group 0;" ::: "memory")

// ---------------------------------------------------------------------------
// Kernel 1: QKV projection (tf32 mma.sync) with FUSED RoPE epilogue.
// CTA tile 128x128, BK=32, double-buffered smem, 8 warps (2x4), warp tile
// 64x32. Scalar smem fragment loads (conflict-free, stride 36).
// Epilogue: RoPE, fold 1/8 scale into Q, store TF32 bit patterns.
// ---------------------------------------------------------------------------
#define QKV_SMEM 73728
__global__ __launch_bounds__(256, 2) void qkv_mma_kernel(
    const float* __restrict__ X, const float* __restrict__ W)
{
    extern __shared__ uint32_t sm32[];
    uint32_t* SA = sm32;          // [buf][128][36]
    uint32_t* SB = sm32 + 9216;   // [buf][128][36]

    const int tid  = threadIdx.x;
    const int lane = tid & 31;
    const int w    = tid >> 5;
    const int wm   = w >> 2;       // 0..1
    const int wn   = w & 3;        // 0..3
    const int g    = lane >> 2;    // 0..7
    const int j    = lane & 3;     // 0..3

    const int m0 = blockIdx.y * 128;
    const int n0 = blockIdx.x * 128;

    float acc[4][4][4];
#pragma unroll
    for (int mt = 0; mt < 4; mt++)
#pragma unroll
        for (int nt = 0; nt < 4; nt++)
#pragma unroll
            for (int e = 0; e < 4; e++) acc[mt][nt][e] = 0.f;

    float4 va[4], vb[4];
#pragma unroll
    for (int it = 0; it < 4; it++) {
        int idx = tid + it * 256;
        int r   = idx >> 3;
        int c4  = (idx & 7) * 4;
        va[it] = *(const float4*)(X + (size_t)(m0 + r) * DM + c4);
        vb[it] = *(const float4*)(W + (size_t)(n0 + r) * DM + c4);
    }
#pragma unroll
    for (int it = 0; it < 4; it++) {
        int idx = tid + it * 256;
        int r   = idx >> 3;
        int c4  = (idx & 7) * 4;
        uint32_t* pa = SA + r * 36 + c4;
        pa[0] = cvt_tf32(va[it].x); pa[1] = cvt_tf32(va[it].y);
        pa[2] = cvt_tf32(va[it].z); pa[3] = cvt_tf32(va[it].w);
        uint32_t* pb = SB + r * 36 + c4;
        pb[0] = cvt_tf32(vb[it].x); pb[1] = cvt_tf32(vb[it].y);
        pb[2] = cvt_tf32(vb[it].z); pb[3] = cvt_tf32(vb[it].w);
    }
    __syncthreads();

    for (int s = 0; s < 32; s++) {
        if (s < 31) {
            const int k0 = (s + 1) * 32;
#pragma unroll
            for (int it = 0; it < 4; it++) {
                int idx = tid + it * 256;
                int r   = idx >> 3;
                int c4  = (idx & 7) * 4;
                va[it] = *(const float4*)(X + (size_t)(m0 + r) * DM + k0 + c4);
                vb[it] = *(const float4*)(W + (size_t)(n0 + r) * DM + k0 + c4);
            }
        }
        const uint32_t* Ab = SA + (s & 1) * 4608;
        const uint32_t* Bb = SB + (s & 1) * 4608;
#pragma unroll
        for (int ks = 0; ks < 4; ks++) {
            const int kk = ks * 8;
            uint32_t af[4][4];
#pragma unroll
            for (int mt = 0; mt < 4; mt++) {
                int row = wm * 64 + mt * 16 + g;
                af[mt][0] = Ab[row * 36 + kk + j];
                af[mt][1] = Ab[(row + 8) * 36 + kk + j];
                af[mt][2] = Ab[row * 36 + kk + j + 4];
                af[mt][3] = Ab[(row + 8) * 36 + kk + j + 4];
            }
#pragma unroll
            for (int nt = 0; nt < 4; nt++) {
                int col = wn * 32 + nt * 8 + g;
                uint32_t bf[2] = { Bb[col * 36 + kk + j], Bb[col * 36 + kk + j + 4] };
#pragma unroll
                for (int mt = 0; mt < 4; mt++)
                    mma_tf32(acc[mt][nt], af[mt], bf);
            }
        }
        if (s < 31) {
            uint32_t* An = SA + ((s + 1) & 1) * 4608;
            uint32_t* Bn = SB + ((s + 1) & 1) * 4608;
#pragma unroll
            for (int it = 0; it < 4; it++) {
                int idx = tid + it * 256;
                int r   = idx >> 3;
                int c4  = (idx & 7) * 4;
                uint32_t* pa = An + r * 36 + c4;
                pa[0] = cvt_tf32(va[it].x); pa[1] = cvt_tf32(va[it].y);
                pa[2] = cvt_tf32(va[it].z); pa[3] = cvt_tf32(va[it].w);
                uint32_t* pb = Bn + r * 36 + c4;
                pb[0] = cvt_tf32(vb[it].x); pb[1] = cvt_tf32(vb[it].y);
                pb[2] = cvt_tf32(vb[it].z); pb[3] = cvt_tf32(vb[it].w);
            }
            __syncthreads();
        }
    }

    // ---- fused RoPE on accumulators (q and k columns only) ----
    if ((wn & 1) == 0) {
        float thc[2][2];
#pragma unroll
        for (int nt = 0; nt < 2; nt++)
#pragma unroll
            for (int e = 0; e < 2; e++) {
                int d = nt * 8 + 2 * j + e;
                thc[nt][e] = powf(10000.0f, -(float)d * (1.0f / 16.0f));
            }
#pragma unroll
        for (int nt = 0; nt < 2; nt++) {
            int col = n0 + wn * 32 + nt * 8 + 2 * j;
            int h   = col / 192;
            int jj  = col - h * 192;
            int t   = jj >> 6;
            if (t < 2) {   // q or k column
#pragma unroll
                for (int mt = 0; mt < 4; mt++) {
#pragma unroll
                    for (int rr = 0; rr < 2; rr++) {
                        int row = m0 + wm * 64 + mt * 16 + g + rr * 8;
                        float lf = (float)(row >> 1);
#pragma unroll
                        for (int e = 0; e < 2; e++) {
                            float sn, cs;
                            sincosf(lf * thc[nt][e], &sn, &cs);
                            float x1 = acc[mt][nt][rr * 2 + e];
                            float x2 = acc[mt][nt + 2][rr * 2 + e];
                            acc[mt][nt][rr * 2 + e]     = x1 * cs - x2 * sn;
                            acc[mt][nt + 2][rr * 2 + e] = x2 * cs + x1 * sn;
                        }
                    }
                }
            }
        }
    }

    // ---- epilogue scatter: convert to tf32 bits (Q gets 1/8 scale) ----
#pragma unroll
    for (int mt = 0; mt < 4; mt++) {
#pragma unroll
        for (int nt = 0; nt < 4; nt++) {
            int col = n0 + wn * 32 + nt * 8 + 2 * j;
            int h   = col / 192;
            int jj  = col - h * 192;
            int t   = jj >> 6;
            int d   = jj & 63;
#pragma unroll
            for (int rr = 0; rr < 2; rr++) {
                int row = m0 + wm * 64 + mt * 16 + g + rr * 8;
                int l = row >> 1, b = row & 1;
                int hb = h * 2 + b;
                float v0 = acc[mt][nt][rr * 2], v1 = acc[mt][nt][rr * 2 + 1];
                if (t == 0) { v0 *= 0.125f; v1 *= 0.125f; }
                uint2 u = make_uint2(cvt_tf32(v0), cvt_tf32(v1));
                uint32_t* dst = (t == 0) ? g_Q : (t == 1) ? g_K : g_V;
                *(uint2*)&dst[(((size_t)hb * L_SEQ) + l) * DK + d] = u;
            }
        }
    }
}

// ---------------------------------------------------------------------------
// Kernel 2: fused flash attention, tf32 mma.sync.
// CTA: 128 q rows x one (h,b). 8 warps x 16 q-rows, 2 CTAs/SM.
// K/V double-buffered in smem, staged via cp.async (no cvt — g_K/g_V are
// already tf32 bits).  ONE __syncthreads per 64-key chunk; chunk kc+1's
// async copy overlaps chunk kc's mma.  P rows warp-private (no sync).
// ---------------------------------------------------------------------------
#define KST 68
#define VST 72
#define KBUF (64 * KST)
#define VBUF (64 * VST)
#define FLASH_SMEM ((2 * KBUF + 2 * VBUF + 128 * KST) * 4)   // 106496 B

__global__ __launch_bounds__(256, 2) void flash_kernel(float* __restrict__ out)
{
    extern __shared__ uint32_t fsm[];
    uint32_t* Kb = fsm;                       // [2][64][KST]
    uint32_t* Vb = fsm + 2 * KBUF;            // [2][64][VST]
    uint32_t* Ps = fsm + 2 * KBUF + 2 * VBUF; // [128][KST]

    const uint32_t kb_s = smem_u32(Kb);
    const uint32_t vb_s = smem_u32(Vb);

    const int tid  = threadIdx.x;
    const int lane = tid & 31;
    const int w    = tid >> 5;     // 0..7
    const int g    = lane >> 2;
    const int j    = lane & 3;

    const int q0 = blockIdx.x * 128;
    const int hb = blockIdx.y;
    const int h  = hb >> 1, b = hb & 1;

    const uint32_t* Qg = g_Q + (size_t)hb * L_SEQ * DK;
    const uint32_t* Kg = g_K + (size_t)hb * L_SEQ * DK;
    const uint32_t* Vg = g_V + (size_t)hb * L_SEQ * DK;

    // staging map: it 0..3 -> row (tid>>4)+16*it, col (tid&15)*4
    const int st_r = tid >> 4;
    const int st_c = (tid & 15) * 4;

#define FL_STAGE(buf, roff)                                                     \
    {                                                                           \
        _Pragma("unroll")                                                       \
        for (int it = 0; it < 4; it++) {                                        \
            int r = st_r + it * 16;                                             \
            CP_ASYNC16(kb_s + ((buf) * KBUF + r * KST + st_c) * 4,              \
                       Kg + ((roff) + r) * DK + st_c);                          \
            CP_ASYNC16(vb_s + ((buf) * VBUF + r * VST + st_c) * 4,              \
                       Vg + ((roff) + r) * DK + st_c);                          \
        }                                                                       \
        CP_COMMIT();                                                            \
    }

    // Q fragments (already scaled tf32 bits) — plain loads
    uint32_t qa[8][4];
    {
        int r0 = q0 + w * 16 + g;
#pragma unroll
        for (int ks = 0; ks < 8; ks++) {
            int c = ks * 8 + j;
            qa[ks][0] = Qg[(size_t)r0 * DK + c];
            qa[ks][1] = Qg[(size_t)(r0 + 8) * DK + c];
            qa[ks][2] = Qg[(size_t)r0 * DK + c + 4];
            qa[ks][3] = Qg[(size_t)(r0 + 8) * DK + c + 4];
        }
    }

    float o[8][4];
#pragma unroll
    for (int nt = 0; nt < 8; nt++)
#pragma unroll
        for (int e = 0; e < 4; e++) o[nt][e] = 0.f;
    float mrow0 = -1e30f, mrow1 = -1e30f;
    float lrow0 = 0.f, lrow1 = 0.f;

    FL_STAGE(0, (size_t)0);   // chunk 0 -> buffer 0

    for (int kc = 0; kc < L_SEQ / 64; kc++) {
        CP_WAIT0();          // my async copies for chunk kc complete
        __syncthreads();     // all threads' copies visible; all done with kc-1

        // overlap: start chunk kc+1 into the other buffer
        if (kc + 1 < L_SEQ / 64) FL_STAGE((kc + 1) & 1, (size_t)(kc + 1) * 64);

        const uint32_t* Ks = Kb + (kc & 1) * KBUF;
        const uint32_t* Vs = Vb + (kc & 1) * VBUF;

        // S = Q K^T  (per warp: 16 x 64)
        float s[8][4];
#pragma unroll
        for (int nt = 0; nt < 8; nt++)
#pragma unroll
            for (int e = 0; e < 4; e++) s[nt][e] = 0.f;
#pragma unroll
        for (int ks = 0; ks < 8; ks++) {
            const int kk = ks * 8;
#pragma unroll
            for (int nt = 0; nt < 8; nt++) {
                uint32_t bf[2] = { Ks[(nt * 8 + g) * KST + kk + j],
                                   Ks[(nt * 8 + g) * KST + kk + j + 4] };
                mma_tf32(s[nt], qa[ks], bf);
            }
        }

        // online softmax (rows g and g+8); exp on MUFU
        float mx0 = -1e30f, mx1 = -1e30f;
#pragma unroll
        for (int nt = 0; nt < 8; nt++) {
            mx0 = fmaxf(mx0, fmaxf(s[nt][0], s[nt][1]));
            mx1 = fmaxf(mx1, fmaxf(s[nt][2], s[nt][3]));
        }
        mx0 = fmaxf(mx0, __shfl_xor_sync(0xffffffffu, mx0, 1));
        mx0 = fmaxf(mx0, __shfl_xor_sync(0xffffffffu, mx0, 2));
        mx1 = fmaxf(mx1, __shfl_xor_sync(0xffffffffu, mx1, 1));
        mx1 = fmaxf(mx1, __shfl_xor_sync(0xffffffffu, mx1, 2));

        float mn0 = fmaxf(mrow0, mx0), mn1 = fmaxf(mrow1, mx1);
        float al0 = __expf(mrow0 - mn0), al1 = __expf(mrow1 - mn1);
        mrow0 = mn0; mrow1 = mn1;

        float rs0 = 0.f, rs1 = 0.f;
#pragma unroll
        for (int nt = 0; nt < 8; nt++) {
            s[nt][0] = __expf(s[nt][0] - mn0);
            s[nt][1] = __expf(s[nt][1] - mn0);
            s[nt][2] = __expf(s[nt][2] - mn1);
            s[nt][3] = __expf(s[nt][3] - mn1);
            rs0 += s[nt][0] + s[nt][1];
            rs1 += s[nt][2] + s[nt][3];
        }
        rs0 += __shfl_xor_sync(0xffffffffu, rs0, 1);
        rs0 += __shfl_xor_sync(0xffffffffu, rs0, 2);
        rs1 += __shfl_xor_sync(0xffffffffu, rs1, 1);
        rs1 += __shfl_xor_sync(0xffffffffu, rs1, 2);
        lrow0 = lrow0 * al0 + rs0;
        lrow1 = lrow1 * al1 + rs1;

#pragma unroll
        for (int nt = 0; nt < 8; nt++) {
            o[nt][0] *= al0; o[nt][1] *= al0;
            o[nt][2] *= al1; o[nt][3] *= al1;
        }

        // write P (tf32) into this warp's private rows — no sync needed
        {
            int pr0 = (w * 16 + g) * KST;
            int pr1 = (w * 16 + g + 8) * KST;
#pragma unroll
            for (int nt = 0; nt < 8; nt++) {
                int c = nt * 8 + 2 * j;
                *(uint2*)&Ps[pr0 + c] = make_uint2(cvt_tf32(s[nt][0]), cvt_tf32(s[nt][1]));
                *(uint2*)&Ps[pr1 + c] = make_uint2(cvt_tf32(s[nt][2]), cvt_tf32(s[nt][3]));
            }
        }

        // O += P V
#pragma unroll
        for (int ks = 0; ks < 8; ks++) {
            const int kk = ks * 8;
            uint32_t pa[4];
            pa[0] = Ps[(w * 16 + g) * KST + kk + j];
            pa[1] = Ps[(w * 16 + g + 8) * KST + kk + j];
            pa[2] = Ps[(w * 16 + g) * KST + kk + j + 4];
            pa[3] = Ps[(w * 16 + g + 8) * KST + kk + j + 4];
#pragma unroll
            for (int nt = 0; nt < 8; nt++) {
                uint32_t bf[2] = { Vs[(kk + j) * VST + nt * 8 + g],
                                   Vs[(kk + j + 4) * VST + nt * 8 + g] };
                mma_tf32(o[nt], pa, bf);
            }
        }
    }

    // normalize and write out: out[l][b][h*64 + d]
    float inv0 = 1.0f / lrow0, inv1 = 1.0f / lrow1;
    int r0 = q0 + w * 16 + g;
#pragma unroll
    for (int nt = 0; nt < 8; nt++) {
        int c = nt * 8 + 2 * j;
        float2 v0 = make_float2(o[nt][0] * inv0, o[nt][1] * inv0);
        *(float2*)(out + ((size_t)r0 * BATCH + b) * DM + h * DK + c) = v0;
        float2 v1 = make_float2(o[nt][2] * inv1, o[nt][3] * inv1);
        *(float2*)(out + ((size_t)(r0 + 8) * BATCH + b) * DM + h * DK + c) = v1;
    }
}

// ---------------------------------------------------------------------------
extern "C" void kernel_launch(void* const* d_in, const int* in_sizes, int n_in,
                              void* d_out, int out_size)
{
    const float* X = (const float*)d_in[0];
    const float* W = (const float*)d_in[1];
    float* out = (float*)d_out;

    cudaFuncSetAttribute(qkv_mma_kernel,
                         cudaFuncAttributeMaxDynamicSharedMemorySize, QKV_SMEM);
    cudaFuncSetAttribute(flash_kernel,
                         cudaFuncAttributeMaxDynamicSharedMemorySize, FLASH_SMEM);

    qkv_mma_kernel<<<dim3(E3 / 128, MROWS / 128), 256, QKV_SMEM>>>(X, W);
    flash_kernel<<<dim3(L_SEQ / 128, HB), 256, FLASH_SMEM>>>(out);
}